// round 14
// baseline (speedup 1.0000x reference)
#include <cuda_runtime.h>
#include <cstdint>

// Problem constants (fixed shapes for this problem)
#define Bc 8
#define Hc 1024
#define Ec 512
#define Vc 32000
#define Tc 100
#define KVc 1536   // H + E   (x_v width)
#define KKc 2560   // 2H + E  (x_k width)

#define GRID_MAIN 296          // 2 blocks per SM on 148 SMs, single wave
// 8000 tiles = 296*27 + 8 -> first 8 blocks take 28 tiles, rest 27
#define MAXW 112               // max vocab words per block (28 tiles * 4)

// Scratch (device globals; no runtime allocation allowed)
__device__ float g_ekval[Bc * Vc];             // e_k values (valid where topic word present)
__device__ float g_psum[GRID_MAIN * Bc];       // per-BLOCK partial sums (gated words EXCLUDED)

// ---------------------------------------------------------------------------
// Kernel 1: main GEMV + topic-mask psum exclusion + tail e_k dots.
//  - proven core: 4 rows x 8 batches per warp-tile, 48 KB xs, double-buffered
//    W loads, butterfly transpose-reduce, natural regs at 2 blocks/SM.
//  - membership mask (~900 B smem) built from one pass over the 800 topic
//    ids; epilogue writes p = exp(tanh(e_v + b_V)) for ALL words but adds to
//    psum only UNGATED words. No dependency on e_k values.
//  - after psum store, warps 0-2 each compute at most one of the 800
//    e_k = x_k . W_K[idx] + b_K[idx] dots -> g_ekval (tail work; other
//    warps have already exited).
// ---------------------------------------------------------------------------
__global__ void __launch_bounds__(256, 2) main_kernel(const float* __restrict__ outp,
                                                      const float* __restrict__ inp,
                                                      const float* __restrict__ ctx,
                                                      const int*   __restrict__ topics,
                                                      const float* __restrict__ WV,
                                                      const float* __restrict__ bV,
                                                      const float* __restrict__ WK,
                                                      const float* __restrict__ bK,
                                                      float* __restrict__ out) {
    __shared__ float xs[Bc * KVc];            // 49152 bytes
    __shared__ float sm_ps[8 * Bc];           // per-warp batch sums
    __shared__ unsigned char smask[Bc * MAXW];// topic-word membership, this block's range

    int tid  = threadIdx.x;
    int warp = tid >> 5;
    int lane = tid & 31;
    int blk  = blockIdx.x;

    int tbase = blk * 27 + (blk < 8 ? blk : 8);
    int tcnt  = 27 + (blk < 8 ? 1 : 0);
    int wlo   = tbase * 4;
    int whi   = wlo + tcnt * 4;

    // Phase 0a: fill xs; zero mask
    for (int i = tid; i < (Bc * KVc) / 4; i += 256) {
        int fi = i * 4;
        int b = fi / KVc;
        int c = fi % KVc;
        float4 v;
        if (c < Hc) v = *(const float4*)(outp + b * Hc + c);
        else        v = *(const float4*)(inp  + b * Ec + (c - Hc));
        *(float4*)(xs + fi) = v;
    }
    for (int i = tid; i < Bc * MAXW; i += 256) smask[i] = 0;
    __syncthreads();

    // Phase 0b: scan the 800 topic ids; mark in-range words
    for (int i = tid; i < Bc * Tc; i += 256) {
        int w = topics[i];
        if (w != 0 && w >= wlo && w < whi)
            smask[(i / Tc) * MAXW + (w - wlo)] = 1;
    }
    __syncthreads();

    // Phase 1: GEMV
    int b = lane & 7;
    int r = lane >> 3;
    float lsum = 0.f;

    #pragma unroll 1
    for (int k = warp; k < tcnt; k += 8) {
        int tile = tbase + k;
        int w0 = tile * 4;
        float acc[32];
        #pragma unroll
        for (int j = 0; j < 32; j++) acc[j] = 0.f;

        const float* Wp = WV + (size_t)w0 * KVc + lane * 4;

        // double-buffered W loads
        float4 wc0 = *(const float4*)(Wp);
        float4 wc1 = *(const float4*)(Wp + KVc);
        float4 wc2 = *(const float4*)(Wp + 2 * KVc);
        float4 wc3 = *(const float4*)(Wp + 3 * KVc);

        #pragma unroll 2
        for (int it = 0; it < 12; it++) {
            float4 wn0, wn1, wn2, wn3;
            if (it < 11) {
                const float* Pn = Wp + (it + 1) * 128;
                wn0 = *(const float4*)(Pn);
                wn1 = *(const float4*)(Pn + KVc);
                wn2 = *(const float4*)(Pn + 2 * KVc);
                wn3 = *(const float4*)(Pn + 3 * KVc);
            }
            int xb = it * 128 + lane * 4;
            #pragma unroll
            for (int bb = 0; bb < 8; bb++) {
                float4 xv = *(const float4*)(xs + bb * KVc + xb);
                acc[0 * 8 + bb] = fmaf(wc0.x, xv.x, acc[0 * 8 + bb]);
                acc[0 * 8 + bb] = fmaf(wc0.y, xv.y, acc[0 * 8 + bb]);
                acc[0 * 8 + bb] = fmaf(wc0.z, xv.z, acc[0 * 8 + bb]);
                acc[0 * 8 + bb] = fmaf(wc0.w, xv.w, acc[0 * 8 + bb]);
                acc[1 * 8 + bb] = fmaf(wc1.x, xv.x, acc[1 * 8 + bb]);
                acc[1 * 8 + bb] = fmaf(wc1.y, xv.y, acc[1 * 8 + bb]);
                acc[1 * 8 + bb] = fmaf(wc1.z, xv.z, acc[1 * 8 + bb]);
                acc[1 * 8 + bb] = fmaf(wc1.w, xv.w, acc[1 * 8 + bb]);
                acc[2 * 8 + bb] = fmaf(wc2.x, xv.x, acc[2 * 8 + bb]);
                acc[2 * 8 + bb] = fmaf(wc2.y, xv.y, acc[2 * 8 + bb]);
                acc[2 * 8 + bb] = fmaf(wc2.z, xv.z, acc[2 * 8 + bb]);
                acc[2 * 8 + bb] = fmaf(wc2.w, xv.w, acc[2 * 8 + bb]);
                acc[3 * 8 + bb] = fmaf(wc3.x, xv.x, acc[3 * 8 + bb]);
                acc[3 * 8 + bb] = fmaf(wc3.y, xv.y, acc[3 * 8 + bb]);
                acc[3 * 8 + bb] = fmaf(wc3.z, xv.z, acc[3 * 8 + bb]);
                acc[3 * 8 + bb] = fmaf(wc3.w, xv.w, acc[3 * 8 + bb]);
            }
            wc0 = wn0; wc1 = wn1; wc2 = wn2; wc3 = wn3;
        }

        // butterfly transpose-reduce: 31 shuffles; lane l ends with sum of acc[l]
        #pragma unroll
        for (int h = 16; h >= 1; h >>= 1) {
            #pragma unroll
            for (int j = 0; j < h; j++) {
                float lo = acc[j];
                float hi = acc[j + h];
                float mine = (lane & h) ? hi : lo;
                float send = (lane & h) ? lo : hi;
                float recv = __shfl_xor_sync(0xffffffffu, send, h);
                acc[j] = mine + recv;
            }
        }

        int w = w0 + r;
        float en = tanhf(acc[0] + __ldg(bV + w));
        float p = __expf(en);
        out[b * Vc + w] = p;
        if (!smask[b * MAXW + (w - wlo)]) lsum += p;   // exclude gated words
    }

    // lanes {l, l^8, l^16, l^24} share batch b = l&7 -> combine, lane<8 writes
    lsum += __shfl_xor_sync(0xffffffffu, lsum, 8);
    lsum += __shfl_xor_sync(0xffffffffu, lsum, 16);
    if (lane < 8) sm_ps[warp * 8 + b] = lsum;
    __syncthreads();

    // block-level deterministic combine: 8 warps -> one value per batch
    if (tid < 8) {
        float s = 0.f;
        #pragma unroll
        for (int wv = 0; wv < 8; wv++) s += sm_ps[wv * 8 + tid];
        g_psum[blockIdx.x * 8 + tid] = s;
    }

    // Phase 2 (tail): e_k dots, warps 0-2 only (other warps exit now)
    {
        int p = -1;
        if (warp < 2)                    p = warp * GRID_MAIN + blk;
        else if (warp == 2 && blk < 208) p = 2 * GRID_MAIN + blk;
        if (p >= 0) {
            int pb  = p / Tc;
            int idx = topics[p];
            if (idx != 0) {
                const float* wrow = WK + (size_t)idx * KKc;
                float s = 0.f;
                #pragma unroll
                for (int i = 0; i < 20; i++) {
                    int c = i * 128 + lane * 4;
                    float4 wv = *(const float4*)(wrow + c);
                    float4 xv;
                    if (c < Hc)            xv = *(const float4*)(outp + pb * Hc + c);
                    else if (c < Hc + Ec)  xv = *(const float4*)(inp  + pb * Ec + (c - Hc));
                    else                   xv = *(const float4*)(ctx  + pb * Hc + (c - Hc - Ec));
                    s += wv.x * xv.x + wv.y * xv.y + wv.z * xv.z + wv.w * xv.w;
                }
                #pragma unroll
                for (int h = 16; h >= 1; h >>= 1) s += __shfl_xor_sync(0xffffffffu, s, h);
                if (lane == 0) g_ekval[pb * Vc + idx] = s + __ldg(bK + idx);
            }
        }
    }
}

// ---------------------------------------------------------------------------
// Kernel 2: fused fix + normalize. grid (125, 8), 256 threads.
// Per batch b: recompute cnt/first for the 100 topic ids (smem O(100^2)),
// pnew = exp(tanh(cnt*e_k)) for first occurrences; D = sum(pnew) fixed order;
// S' = psum reduce (gated words excluded by main); rinv = 1/(S'+D).
// Then write this block's 256-word slice: (patched ? pnew : out[i]) * rinv.
// No cross-block reads of patched values -> race-free single kernel.
// ---------------------------------------------------------------------------
__global__ void __launch_bounds__(256) fixnorm_kernel(const int* __restrict__ topics,
                                                      float* __restrict__ out) {
    int b   = blockIdx.y;
    int tid = threadIdx.x;
    __shared__ int   tw[Tc];
    __shared__ float pn[Tc + 28];   // pnew per topic slot (0 if not first/pad); padded
    __shared__ float ssum[8];
    __shared__ float srinv;

    if (tid < Tc) tw[tid] = topics[b * Tc + tid];
    if (tid < Tc + 28) pn[tid] = 0.f;
    __syncthreads();

    if (tid < Tc) {
        int w = tw[tid];
        if (w != 0) {
            bool first = true;
            int cnt = 0;
            #pragma unroll 4
            for (int j = 0; j < Tc; j++) {
                if (tw[j] == w) {
                    cnt++;
                    if (j < tid) first = false;
                }
            }
            if (first)
                pn[tid] = __expf(tanhf((float)cnt * g_ekval[b * Vc + w]));
        }
    }

    // psum reduce (296 values, fixed order)
    float s = 0.f;
    if (tid < GRID_MAIN)       s += g_psum[tid * 8 + b];
    if (tid + 256 < GRID_MAIN) s += g_psum[(tid + 256) * 8 + b];
    #pragma unroll
    for (int h = 16; h >= 1; h >>= 1) s += __shfl_xor_sync(0xffffffffu, s, h);
    if ((tid & 31) == 0) ssum[tid >> 5] = s;
    __syncthreads();

    if (tid == 0) {
        float S = 0.f;
        #pragma unroll
        for (int w = 0; w < 8; w++) S += ssum[w];
        float D = 0.f;
        #pragma unroll 4
        for (int j = 0; j < Tc; j++) D += pn[j];
        srinv = 1.0f / (S + D);
    }
    __syncthreads();

    // write slice: patched words take pnew, others the ungated p from main
    int wcol = blockIdx.x * 256 + tid;   // 125*256 == 32000 exactly
    float val = out[b * Vc + wcol];
    float rinv = srinv;
    #pragma unroll 4
    for (int j = 0; j < Tc; j++) {
        if (tw[j] == wcol) {
            float pj = pn[j];
            if (pj > 0.f) val = pj;   // pnew = exp(tanh(.)) > 0 always
        }
    }
    out[b * Vc + wcol] = val * rinv;
}

// ---------------------------------------------------------------------------
// Launch (2 kernels)
// Input order: output, input_step, context, topic_indexs, [topic_length],
//              W_V, b_V, W_K, b_K
// ---------------------------------------------------------------------------
extern "C" void kernel_launch(void* const* d_in, const int* in_sizes, int n_in,
                              void* d_out, int out_size) {
    const float* outp   = (const float*)d_in[0];
    const float* inp    = (const float*)d_in[1];
    const float* ctx    = (const float*)d_in[2];
    const int*   topics = (const int*)d_in[3];

    int base = 4;
    if (n_in >= 9 && in_sizes[4] <= 4) base = 5;   // skip topic_length scalar

    const float* WV = (const float*)d_in[base + 0];
    const float* bV = (const float*)d_in[base + 1];
    const float* WK = (const float*)d_in[base + 2];
    const float* bK = (const float*)d_in[base + 3];
    float* out = (float*)d_out;

    main_kernel<<<GRID_MAIN, 256>>>(outp, inp, ctx, topics, WV, bV, WK, bK, out);
    fixnorm_kernel<<<dim3(125, Bc), 256>>>(topics, out);
}

// round 15
// speedup vs baseline: 1.0750x; 1.0750x over previous
#include <cuda_runtime.h>
#include <cstdint>

// Problem constants (fixed shapes for this problem)
#define Bc 8
#define Hc 1024
#define Ec 512
#define Vc 32000
#define Tc 100
#define KVc 1536   // H + E   (x_v width)
#define KKc 2560   // 2H + E  (x_k width)

#define GRID_MAIN 296          // 2 blocks per SM on 148 SMs, single wave
// 8000 tiles = 296*27 + 8 -> first 8 blocks take 28 tiles, rest 27
#define MAXW 112               // max vocab words per block (28 tiles * 4)

// Scratch (device globals; no runtime allocation allowed)
__device__ float g_ekval[Bc * Vc];             // e_k values (valid where topic word present)
__device__ float g_psum[GRID_MAIN * Bc];       // per-BLOCK partial sums (gated words EXCLUDED)

// ---------------------------------------------------------------------------
// Kernel 1: main GEMV + topic-mask psum exclusion + tail e_k dots.
// (unchanged from R14 — validated structure)
// ---------------------------------------------------------------------------
__global__ void __launch_bounds__(256, 2) main_kernel(const float* __restrict__ outp,
                                                      const float* __restrict__ inp,
                                                      const float* __restrict__ ctx,
                                                      const int*   __restrict__ topics,
                                                      const float* __restrict__ WV,
                                                      const float* __restrict__ bV,
                                                      const float* __restrict__ WK,
                                                      const float* __restrict__ bK,
                                                      float* __restrict__ out) {
    __shared__ float xs[Bc * KVc];            // 49152 bytes
    __shared__ float sm_ps[8 * Bc];           // per-warp batch sums
    __shared__ unsigned char smask[Bc * MAXW];// topic-word membership, this block's range

    int tid  = threadIdx.x;
    int warp = tid >> 5;
    int lane = tid & 31;
    int blk  = blockIdx.x;

    int tbase = blk * 27 + (blk < 8 ? blk : 8);
    int tcnt  = 27 + (blk < 8 ? 1 : 0);
    int wlo   = tbase * 4;
    int whi   = wlo + tcnt * 4;

    // Phase 0a: fill xs; zero mask
    for (int i = tid; i < (Bc * KVc) / 4; i += 256) {
        int fi = i * 4;
        int b = fi / KVc;
        int c = fi % KVc;
        float4 v;
        if (c < Hc) v = *(const float4*)(outp + b * Hc + c);
        else        v = *(const float4*)(inp  + b * Ec + (c - Hc));
        *(float4*)(xs + fi) = v;
    }
    for (int i = tid; i < Bc * MAXW; i += 256) smask[i] = 0;
    __syncthreads();

    // Phase 0b: scan the 800 topic ids; mark in-range words
    for (int i = tid; i < Bc * Tc; i += 256) {
        int w = topics[i];
        if (w != 0 && w >= wlo && w < whi)
            smask[(i / Tc) * MAXW + (w - wlo)] = 1;
    }
    __syncthreads();

    // Phase 1: GEMV
    int b = lane & 7;
    int r = lane >> 3;
    float lsum = 0.f;

    #pragma unroll 1
    for (int k = warp; k < tcnt; k += 8) {
        int tile = tbase + k;
        int w0 = tile * 4;
        float acc[32];
        #pragma unroll
        for (int j = 0; j < 32; j++) acc[j] = 0.f;

        const float* Wp = WV + (size_t)w0 * KVc + lane * 4;

        // double-buffered W loads
        float4 wc0 = *(const float4*)(Wp);
        float4 wc1 = *(const float4*)(Wp + KVc);
        float4 wc2 = *(const float4*)(Wp + 2 * KVc);
        float4 wc3 = *(const float4*)(Wp + 3 * KVc);

        #pragma unroll 2
        for (int it = 0; it < 12; it++) {
            float4 wn0, wn1, wn2, wn3;
            if (it < 11) {
                const float* Pn = Wp + (it + 1) * 128;
                wn0 = *(const float4*)(Pn);
                wn1 = *(const float4*)(Pn + KVc);
                wn2 = *(const float4*)(Pn + 2 * KVc);
                wn3 = *(const float4*)(Pn + 3 * KVc);
            }
            int xb = it * 128 + lane * 4;
            #pragma unroll
            for (int bb = 0; bb < 8; bb++) {
                float4 xv = *(const float4*)(xs + bb * KVc + xb);
                acc[0 * 8 + bb] = fmaf(wc0.x, xv.x, acc[0 * 8 + bb]);
                acc[0 * 8 + bb] = fmaf(wc0.y, xv.y, acc[0 * 8 + bb]);
                acc[0 * 8 + bb] = fmaf(wc0.z, xv.z, acc[0 * 8 + bb]);
                acc[0 * 8 + bb] = fmaf(wc0.w, xv.w, acc[0 * 8 + bb]);
                acc[1 * 8 + bb] = fmaf(wc1.x, xv.x, acc[1 * 8 + bb]);
                acc[1 * 8 + bb] = fmaf(wc1.y, xv.y, acc[1 * 8 + bb]);
                acc[1 * 8 + bb] = fmaf(wc1.z, xv.z, acc[1 * 8 + bb]);
                acc[1 * 8 + bb] = fmaf(wc1.w, xv.w, acc[1 * 8 + bb]);
                acc[2 * 8 + bb] = fmaf(wc2.x, xv.x, acc[2 * 8 + bb]);
                acc[2 * 8 + bb] = fmaf(wc2.y, xv.y, acc[2 * 8 + bb]);
                acc[2 * 8 + bb] = fmaf(wc2.z, xv.z, acc[2 * 8 + bb]);
                acc[2 * 8 + bb] = fmaf(wc2.w, xv.w, acc[2 * 8 + bb]);
                acc[3 * 8 + bb] = fmaf(wc3.x, xv.x, acc[3 * 8 + bb]);
                acc[3 * 8 + bb] = fmaf(wc3.y, xv.y, acc[3 * 8 + bb]);
                acc[3 * 8 + bb] = fmaf(wc3.z, xv.z, acc[3 * 8 + bb]);
                acc[3 * 8 + bb] = fmaf(wc3.w, xv.w, acc[3 * 8 + bb]);
            }
            wc0 = wn0; wc1 = wn1; wc2 = wn2; wc3 = wn3;
        }

        // butterfly transpose-reduce: 31 shuffles; lane l ends with sum of acc[l]
        #pragma unroll
        for (int h = 16; h >= 1; h >>= 1) {
            #pragma unroll
            for (int j = 0; j < h; j++) {
                float lo = acc[j];
                float hi = acc[j + h];
                float mine = (lane & h) ? hi : lo;
                float send = (lane & h) ? lo : hi;
                float recv = __shfl_xor_sync(0xffffffffu, send, h);
                acc[j] = mine + recv;
            }
        }

        int w = w0 + r;
        float en = tanhf(acc[0] + __ldg(bV + w));
        float p = __expf(en);
        out[b * Vc + w] = p;
        if (!smask[b * MAXW + (w - wlo)]) lsum += p;   // exclude gated words
    }

    // lanes {l, l^8, l^16, l^24} share batch b = l&7 -> combine, lane<8 writes
    lsum += __shfl_xor_sync(0xffffffffu, lsum, 8);
    lsum += __shfl_xor_sync(0xffffffffu, lsum, 16);
    if (lane < 8) sm_ps[warp * 8 + b] = lsum;
    __syncthreads();

    // block-level deterministic combine: 8 warps -> one value per batch
    if (tid < 8) {
        float s = 0.f;
        #pragma unroll
        for (int wv = 0; wv < 8; wv++) s += sm_ps[wv * 8 + tid];
        g_psum[blockIdx.x * 8 + tid] = s;
    }

    // Phase 2 (tail): e_k dots, warps 0-2 only (other warps exit now)
    {
        int p = -1;
        if (warp < 2)                    p = warp * GRID_MAIN + blk;
        else if (warp == 2 && blk < 208) p = 2 * GRID_MAIN + blk;
        if (p >= 0) {
            int pb  = p / Tc;
            int idx = topics[p];
            if (idx != 0) {
                const float* wrow = WK + (size_t)idx * KKc;
                float s = 0.f;
                #pragma unroll
                for (int i = 0; i < 20; i++) {
                    int c = i * 128 + lane * 4;
                    float4 wv = *(const float4*)(wrow + c);
                    float4 xv;
                    if (c < Hc)            xv = *(const float4*)(outp + pb * Hc + c);
                    else if (c < Hc + Ec)  xv = *(const float4*)(inp  + pb * Ec + (c - Hc));
                    else                   xv = *(const float4*)(ctx  + pb * Hc + (c - Hc - Ec));
                    s += wv.x * xv.x + wv.y * xv.y + wv.z * xv.z + wv.w * xv.w;
                }
                #pragma unroll
                for (int h = 16; h >= 1; h >>= 1) s += __shfl_xor_sync(0xffffffffu, s, h);
                if (lane == 0) g_ekval[pb * Vc + idx] = s + __ldg(bK + idx);
            }
        }
    }
}

// ---------------------------------------------------------------------------
// Kernel 2: fused fix + normalize. grid (125, 8), 256 threads.
// Scatter version: <=100 smem scatter stores per block mark this slice's
// patched words; each thread then does ONE smem read (no per-element scan).
// ---------------------------------------------------------------------------
__global__ void __launch_bounds__(256) fixnorm_kernel(const int* __restrict__ topics,
                                                      float* __restrict__ out) {
    int b   = blockIdx.y;
    int tid = threadIdx.x;
    __shared__ int   tw[Tc];
    __shared__ float pn[Tc];        // pnew per topic slot (0 if not first/pad)
    __shared__ float patch[256];    // pnew scattered into this block's slice (0 = none)
    __shared__ float ssum[8];
    __shared__ float srinv;

    if (tid < Tc) tw[tid] = topics[b * Tc + tid];
    if (tid < Tc) pn[tid] = 0.f;
    patch[tid] = 0.f;
    __syncthreads();

    if (tid < Tc) {
        int w = tw[tid];
        if (w != 0) {
            bool first = true;
            int cnt = 0;
            #pragma unroll 4
            for (int j = 0; j < Tc; j++) {
                if (tw[j] == w) {
                    cnt++;
                    if (j < tid) first = false;
                }
            }
            if (first)
                pn[tid] = __expf(tanhf((float)cnt * g_ekval[b * Vc + w]));
        }
    }

    // psum reduce (296 values, fixed order)
    float s = 0.f;
    if (tid < GRID_MAIN)       s += g_psum[tid * 8 + b];
    if (tid + 256 < GRID_MAIN) s += g_psum[(tid + 256) * 8 + b];
    #pragma unroll
    for (int h = 16; h >= 1; h >>= 1) s += __shfl_xor_sync(0xffffffffu, s, h);
    if ((tid & 31) == 0) ssum[tid >> 5] = s;
    __syncthreads();

    if (tid == 0) {
        float S = 0.f;
        #pragma unroll
        for (int w = 0; w < 8; w++) S += ssum[w];
        float D = 0.f;
        #pragma unroll 4
        for (int j = 0; j < Tc; j++) D += pn[j];
        srinv = 1.0f / (S + D);
    }

    // scatter patched words that fall inside this block's 256-word slice
    int base = blockIdx.x * 256;
    if (tid < Tc) {
        float pj = pn[tid];
        if (pj > 0.f) {
            int off = tw[tid] - base;
            if (off >= 0 && off < 256) patch[off] = pj;   // distinct first-occurrence words
        }
    }
    __syncthreads();

    // write slice: one smem read per element
    int wcol = base + tid;               // 125*256 == 32000 exactly
    float pv = patch[tid];
    float val = (pv > 0.f) ? pv : out[b * Vc + wcol];
    out[b * Vc + wcol] = val * srinv;
}

// ---------------------------------------------------------------------------
// Launch (2 kernels)
// Input order: output, input_step, context, topic_indexs, [topic_length],
//              W_V, b_V, W_K, b_K
// ---------------------------------------------------------------------------
extern "C" void kernel_launch(void* const* d_in, const int* in_sizes, int n_in,
                              void* d_out, int out_size) {
    const float* outp   = (const float*)d_in[0];
    const float* inp    = (const float*)d_in[1];
    const float* ctx    = (const float*)d_in[2];
    const int*   topics = (const int*)d_in[3];

    int base = 4;
    if (n_in >= 9 && in_sizes[4] <= 4) base = 5;   // skip topic_length scalar

    const float* WV = (const float*)d_in[base + 0];
    const float* bV = (const float*)d_in[base + 1];
    const float* WK = (const float*)d_in[base + 2];
    const float* bK = (const float*)d_in[base + 3];
    float* out = (float*)d_out;

    main_kernel<<<GRID_MAIN, 256>>>(outp, inp, ctx, topics, WV, bV, WK, bK, out);
    fixnorm_kernel<<<dim3(125, Bc), 256>>>(topics, out);
}